// round 1
// baseline (speedup 1.0000x reference)
#include <cuda_runtime.h>
#include <math.h>

#define B_    2
#define NQ    1024
#define NK    2048
#define DIM_  512
#define HID_  512
#define H_    8
#define HD_   64
#define RBH   64

// Static device scratch (no runtime allocation allowed)
__device__ float g_Q[(size_t)B_ * NQ * HID_];          //  4 MB
__device__ float g_K[(size_t)B_ * NK * HID_];          //  8 MB
__device__ float g_V[(size_t)B_ * NK * HID_];          //  8 MB
__device__ float g_attn[(size_t)B_ * NQ * HID_];       //  4 MB
__device__ float g_bias[(size_t)B_ * H_ * NQ * NK];    // 134 MB  [B,H,Nq,Nk]

// ---------------------------------------------------------------------------
// Generic fp32 GEMM: C[M,N] = A[M,K] @ B[K,N], row-major, M%64==0, N%64==0,
// K%16==0. 64x64 block tile, BK=16, 256 threads, 4x4 micro-tile per thread.
// ---------------------------------------------------------------------------
#define BM 64
#define BN 64
#define BKK 16

__global__ __launch_bounds__(256) void gemm_kernel(
    const float* __restrict__ A, const float* __restrict__ Bm,
    float* __restrict__ C, int M, int N, int K)
{
    __shared__ float As[BKK][BM + 4];
    __shared__ float Bs[BKK][BN + 4];

    const int tid = threadIdx.x;
    const int tx  = tid & 15;
    const int ty  = tid >> 4;
    const int row0 = blockIdx.y * BM;
    const int col0 = blockIdx.x * BN;

    float acc[4][4] = {};

    for (int k0 = 0; k0 < K; k0 += BKK) {
        // A tile: 64 rows x 16 cols -> As[k][m]
        {
            const int m = tid >> 2;      // 0..63
            const int v = tid & 3;       // 0..3 (float4 within the 16-wide k slab)
            float4 a = *reinterpret_cast<const float4*>(
                &A[(size_t)(row0 + m) * K + k0 + v * 4]);
            As[v * 4 + 0][m] = a.x;
            As[v * 4 + 1][m] = a.y;
            As[v * 4 + 2][m] = a.z;
            As[v * 4 + 3][m] = a.w;
        }
        // B tile: 16 rows x 64 cols -> Bs[k][n]
        {
            const int kk = tid >> 4;     // 0..15
            const int v  = tid & 15;     // 0..15
            float4 b = *reinterpret_cast<const float4*>(
                &Bm[(size_t)(k0 + kk) * N + col0 + v * 4]);
            *reinterpret_cast<float4*>(&Bs[kk][v * 4]) = b;
        }
        __syncthreads();

        #pragma unroll
        for (int kk = 0; kk < BKK; kk++) {
            float4 a4 = *reinterpret_cast<const float4*>(&As[kk][ty * 4]);
            float4 b4 = *reinterpret_cast<const float4*>(&Bs[kk][tx * 4]);
            float av[4] = {a4.x, a4.y, a4.z, a4.w};
            float bv[4] = {b4.x, b4.y, b4.z, b4.w};
            #pragma unroll
            for (int i = 0; i < 4; i++)
                #pragma unroll
                for (int j = 0; j < 4; j++)
                    acc[i][j] = fmaf(av[i], bv[j], acc[i][j]);
        }
        __syncthreads();
    }

    #pragma unroll
    for (int i = 0; i < 4; i++) {
        float4 o = make_float4(acc[i][0], acc[i][1], acc[i][2], acc[i][3]);
        *reinterpret_cast<float4*>(
            &C[(size_t)(row0 + ty * 4 + i) * N + col0 + tx * 4]) = o;
    }
}

// ---------------------------------------------------------------------------
// Distance-MLP bias, computed ONCE per (b,q,k) for all 8 heads.
// bias[b,h,q,k] = b2[h] + sum_j silu(d*W1[j] + b1[j]) * W2[j,h]
// grid: (NK/256, NQ, B), block 256 (one thread per k)
// ---------------------------------------------------------------------------
__global__ __launch_bounds__(256) void bias_kernel(
    const float* __restrict__ qc, const float* __restrict__ kc,
    const float* __restrict__ W1, const float* __restrict__ b1,
    const float* __restrict__ W2, const float* __restrict__ b2)
{
    __shared__ float sW1[RBH], sb1[RBH], sW2[RBH * H_], sb2[H_], sqc[3];

    const int b = blockIdx.z;
    const int q = blockIdx.y;
    const int k = blockIdx.x * 256 + threadIdx.x;
    const int t = threadIdx.x;

    if (t < RBH) { sW1[t] = W1[t]; sb1[t] = b1[t]; }
    for (int i = t; i < RBH * H_; i += 256) sW2[i] = W2[i];
    if (t < H_) sb2[t] = b2[t];
    if (t < 3)  sqc[t] = qc[((size_t)b * NQ + q) * 3 + t];
    __syncthreads();

    const size_t kcbase = ((size_t)b * NK + k) * 3;
    float dx = sqc[0] - kc[kcbase + 0];
    float dy = sqc[1] - kc[kcbase + 1];
    float dz = sqc[2] - kc[kcbase + 2];
    float d  = sqrtf(fmaf(dx, dx, fmaf(dy, dy, dz * dz)));

    float o[H_];
    #pragma unroll
    for (int hh = 0; hh < H_; hh++) o[hh] = sb2[hh];

    #pragma unroll 8
    for (int j = 0; j < RBH; j++) {
        float x = fmaf(d, sW1[j], sb1[j]);
        float s = __fdividef(x, 1.0f + __expf(-x));   // silu
        #pragma unroll
        for (int hh = 0; hh < H_; hh++)
            o[hh] = fmaf(s, sW2[j * H_ + hh], o[hh]);
    }

    #pragma unroll
    for (int hh = 0; hh < H_; hh++)
        g_bias[(((size_t)b * H_ + hh) * NQ + q) * NK + k] = o[hh];
}

// ---------------------------------------------------------------------------
// Flash attention (online softmax), one thread per q row, K/V tiles in SMEM.
// grid: (NQ/QT, H, B), block QT threads.
// ---------------------------------------------------------------------------
#define QT 128
#define KT 32

__global__ __launch_bounds__(QT) void attn_kernel()
{
    __shared__ float Ks[KT][HD_];
    __shared__ float Vs[KT][HD_];

    const int b = blockIdx.z;
    const int h = blockIdx.y;
    const int q = blockIdx.x * QT + threadIdx.x;
    const float scale = 0.125f;  // HD^-0.5 = 1/8

    const float* qrow = g_Q + ((size_t)(b * NQ + q)) * HID_ + h * HD_;
    float qr[HD_];
    #pragma unroll
    for (int d4 = 0; d4 < HD_; d4 += 4) {
        float4 v = *reinterpret_cast<const float4*>(&qrow[d4]);
        qr[d4] = v.x * scale; qr[d4+1] = v.y * scale;
        qr[d4+2] = v.z * scale; qr[d4+3] = v.w * scale;
    }

    float acc[HD_];
    #pragma unroll
    for (int d = 0; d < HD_; d++) acc[d] = 0.f;
    float mrun = -INFINITY, lrun = 0.f;

    const float* brow = g_bias + (((size_t)b * H_ + h) * NQ + q) * NK;
    const float* Kp = g_K + ((size_t)b * NK) * HID_ + h * HD_;
    const float* Vp = g_V + ((size_t)b * NK) * HID_ + h * HD_;

    for (int k0 = 0; k0 < NK; k0 += KT) {
        __syncthreads();
        for (int i = threadIdx.x; i < KT * HD_ / 4; i += QT) {
            const int kk = i >> 4;
            const int d4 = (i & 15) * 4;
            *reinterpret_cast<float4*>(&Ks[kk][d4]) =
                *reinterpret_cast<const float4*>(&Kp[(size_t)(k0 + kk) * HID_ + d4]);
            *reinterpret_cast<float4*>(&Vs[kk][d4]) =
                *reinterpret_cast<const float4*>(&Vp[(size_t)(k0 + kk) * HID_ + d4]);
        }
        __syncthreads();

        #pragma unroll 2
        for (int kk = 0; kk < KT; kk++) {
            float s = brow[k0 + kk];
            #pragma unroll
            for (int d4 = 0; d4 < HD_; d4 += 4) {
                float4 kv = *reinterpret_cast<const float4*>(&Ks[kk][d4]);
                s = fmaf(qr[d4],   kv.x, s);
                s = fmaf(qr[d4+1], kv.y, s);
                s = fmaf(qr[d4+2], kv.z, s);
                s = fmaf(qr[d4+3], kv.w, s);
            }
            if (s > mrun) {   // rare: rescale running state
                float corr = __expf(mrun - s);
                lrun *= corr;
                #pragma unroll
                for (int d = 0; d < HD_; d++) acc[d] *= corr;
                mrun = s;
            }
            float p = __expf(s - mrun);
            lrun += p;
            #pragma unroll
            for (int d4 = 0; d4 < HD_; d4 += 4) {
                float4 vv = *reinterpret_cast<const float4*>(&Vs[kk][d4]);
                acc[d4]   = fmaf(p, vv.x, acc[d4]);
                acc[d4+1] = fmaf(p, vv.y, acc[d4+1]);
                acc[d4+2] = fmaf(p, vv.z, acc[d4+2]);
                acc[d4+3] = fmaf(p, vv.w, acc[d4+3]);
            }
        }
    }

    const float inv = __fdividef(1.f, lrun);
    float* orow = g_attn + ((size_t)(b * NQ + q)) * HID_ + h * HD_;
    #pragma unroll
    for (int d4 = 0; d4 < HD_; d4 += 4) {
        float4 o = make_float4(acc[d4] * inv, acc[d4+1] * inv,
                               acc[d4+2] * inv, acc[d4+3] * inv);
        *reinterpret_cast<float4*>(&orow[d4]) = o;
    }
}

// ---------------------------------------------------------------------------
extern "C" void kernel_launch(void* const* d_in, const int* in_sizes, int n_in,
                              void* d_out, int out_size)
{
    const float* q_in      = (const float*)d_in[0];
    const float* kv_in     = (const float*)d_in[1];
    const float* q_coords  = (const float*)d_in[2];
    const float* kv_coords = (const float*)d_in[3];
    const float* Wq        = (const float*)d_in[4];
    const float* Wk        = (const float*)d_in[5];
    const float* Wv        = (const float*)d_in[6];
    const float* Wo        = (const float*)d_in[7];
    const float* W1        = (const float*)d_in[8];
    const float* b1        = (const float*)d_in[9];
    const float* W2        = (const float*)d_in[10];
    const float* b2        = (const float*)d_in[11];
    float* out             = (float*)d_out;

    float *Qp, *Kp, *Vp, *Ap;
    cudaGetSymbolAddress((void**)&Qp, g_Q);
    cudaGetSymbolAddress((void**)&Kp, g_K);
    cudaGetSymbolAddress((void**)&Vp, g_V);
    cudaGetSymbolAddress((void**)&Ap, g_attn);

    // Projections
    gemm_kernel<<<dim3(HID_ / BN, (B_ * NQ) / BM), 256>>>(q_in, Wq, Qp, B_ * NQ, HID_, DIM_);
    gemm_kernel<<<dim3(HID_ / BN, (B_ * NK) / BM), 256>>>(kv_in, Wk, Kp, B_ * NK, HID_, DIM_);
    gemm_kernel<<<dim3(HID_ / BN, (B_ * NK) / BM), 256>>>(kv_in, Wv, Vp, B_ * NK, HID_, DIM_);

    // Distance-MLP bias (all heads at once)
    bias_kernel<<<dim3(NK / 256, NQ, B_), 256>>>(q_coords, kv_coords, W1, b1, W2, b2);

    // Flash attention
    attn_kernel<<<dim3(NQ / QT, H_, B_), QT>>>();

    // Output projection
    gemm_kernel<<<dim3(DIM_ / BN, (B_ * NQ) / BM), 256>>>(Ap, Wo, out, B_ * NQ, DIM_, HID_);
}